// round 2
// baseline (speedup 1.0000x reference)
#include <cuda_runtime.h>
#include <cuda_bf16.h>
#include <cstdint>

// Problem dims
#define BSZ   512
#define TSEQ  512
#define IDIM  128
#define HDIM  512
#define NGATE 2048
#define ODIM  128
#define KDIM  640   // I + H

// Tiling
#define MB_TILE 64      // batch rows per CTA
#define HC      32      // h-cols per CTA
#define NT      128     // z-cols per CTA (4 gates x HC)
#define NB_CNT  16      // HDIM / HC
#define MB_CNT  8       // BSZ / MB_TILE
#define NCTA    128
#define KC      32      // k chunk
#define NKC     20      // KDIM / KC
#define SA      40      // smem row stride (elements); conflict-free for frag LDS
#define ZSTR    132     // 4*33
#define THREADS 256

#define ASZ_E   (MB_TILE*SA)            // 2560
#define BSZ_E   (NT*SA)                 // 5120
#define BUF_E   (2*ASZ_E + 2*BSZ_E)     // 15360 elems (Ahi,Alo,Bhi,Blo)
#define SMEM_BYTES (2*BUF_E*2 + MB_TILE*ZSTR*4)   // 61440 + 33792 = 95232

// ------------- device scratch (allocations are forbidden) -------------
__device__ __nv_bfloat16 g_xhi[(size_t)BSZ*TSEQ*IDIM];
__device__ __nv_bfloat16 g_xlo[(size_t)BSZ*TSEQ*IDIM];
__device__ __nv_bfloat16 g_whi[(size_t)NB_CNT*NT*KDIM];
__device__ __nv_bfloat16 g_wlo[(size_t)NB_CNT*NT*KDIM];
__device__ __nv_bfloat16 g_hhi[2][(size_t)BSZ*HDIM];
__device__ __nv_bfloat16 g_hlo[2][(size_t)BSZ*HDIM];
__device__ unsigned int  g_bar_count;
__device__ unsigned int  g_bar_gen;

// ------------- helpers -------------
__device__ __forceinline__ void split_bf16(float v, __nv_bfloat16& hi, __nv_bfloat16& lo) {
    hi = __float2bfloat16(v);
    lo = __float2bfloat16(v - __bfloat162float(hi));
}
__device__ __forceinline__ float sigf(float x) {
    return __fdividef(1.0f, 1.0f + __expf(-x));
}
__device__ __forceinline__ float tanh_(float x) {
    return 2.0f * sigf(2.0f * x) - 1.0f;
}
__device__ __forceinline__ void cp16(void* smem_dst, const void* gsrc) {
    uint32_t s = (uint32_t)__cvta_generic_to_shared(smem_dst);
    asm volatile("cp.async.cg.shared.global [%0], [%1], 16;\n" :: "r"(s), "l"(gsrc));
}
__device__ __forceinline__ void cp_commit() { asm volatile("cp.async.commit_group;\n"); }
__device__ __forceinline__ void cp_wait0() { asm volatile("cp.async.wait_group 0;\n"); }

__device__ __forceinline__ void mma16816(float* c, const uint32_t* a, uint32_t b0, uint32_t b1) {
    asm volatile(
        "mma.sync.aligned.m16n8k16.row.col.f32.bf16.bf16.f32 "
        "{%0,%1,%2,%3},{%4,%5,%6,%7},{%8,%9},{%0,%1,%2,%3};\n"
        : "+f"(c[0]), "+f"(c[1]), "+f"(c[2]), "+f"(c[3])
        : "r"(a[0]), "r"(a[1]), "r"(a[2]), "r"(a[3]), "r"(b0), "r"(b1));
}

__device__ __forceinline__ void grid_barrier() {
    __syncthreads();
    if (threadIdx.x == 0) {
        __threadfence();
        unsigned gen = *((volatile unsigned*)&g_bar_gen);
        unsigned a = atomicAdd(&g_bar_count, 1u);
        if (a == NCTA - 1u) {
            g_bar_count = 0u;
            __threadfence();
            atomicAdd(&g_bar_gen, 1u);
        } else {
            while (*((volatile unsigned*)&g_bar_gen) == gen) { __nanosleep(64); }
        }
        __threadfence();
    }
    __syncthreads();
}

// ------------- setup kernels -------------
__global__ void split_x_kernel(const float* __restrict__ x) {
    size_t idx = (size_t)blockIdx.x * blockDim.x + threadIdx.x;
    if (idx >= (size_t)BSZ * TSEQ * IDIM) return;
    __nv_bfloat16 hi, lo;
    split_bf16(x[idx], hi, lo);
    g_xhi[idx] = hi; g_xlo[idx] = lo;
}

// pack W=[Wx;Wh] to [nb][n][k] (k contiguous), n = q*32+j <-> col q*HDIM+nb*32+j
__global__ void pack_w_kernel(const float* __restrict__ Wx, const float* __restrict__ Wh) {
    size_t idx = (size_t)blockIdx.x * blockDim.x + threadIdx.x;
    if (idx >= (size_t)NB_CNT * NT * KDIM) return;
    int k  = (int)(idx % KDIM);
    int n  = (int)((idx / KDIM) % NT);
    int nb = (int)(idx / ((size_t)KDIM * NT));
    int q = n >> 5, j = n & 31;
    int col = q * HDIM + nb * HC + j;
    float v = (k < IDIM) ? Wx[(size_t)k * NGATE + col]
                         : Wh[(size_t)(k - IDIM) * NGATE + col];
    __nv_bfloat16 hi, lo;
    split_bf16(v, hi, lo);
    g_whi[idx] = hi; g_wlo[idx] = lo;
}

__global__ void zero_h_kernel() {
    size_t idx = (size_t)blockIdx.x * blockDim.x + threadIdx.x;
    if (idx >= (size_t)BSZ * HDIM) return;
    g_hhi[1][idx] = __float2bfloat16(0.0f);
    g_hlo[1][idx] = __float2bfloat16(0.0f);
}

// ------------- staging: one K-chunk (A 64x32 + B 128x32, hi & lo) -------------
__device__ __forceinline__ void stage_chunk(int kc, __nv_bfloat16* buf,
                                            int t, int rbuf, int b0, int nb, int tid) {
    __nv_bfloat16* Ah = buf;
    __nv_bfloat16* Al = buf + ASZ_E;
    __nv_bfloat16* Bh = buf + 2 * ASZ_E;
    __nv_bfloat16* Bl = buf + 2 * ASZ_E + BSZ_E;
    // A: row = tid>>2, kl = (tid&3)*8
    int row = tid >> 2;
    int kl  = (tid & 3) * 8;
    int kg  = kc * KC + kl;
    const __nv_bfloat16 *sH, *sL;
    if (kg < IDIM) {
        size_t o = ((size_t)(b0 + row) * TSEQ + t) * IDIM + kg;
        sH = g_xhi + o; sL = g_xlo + o;
    } else {
        size_t o = (size_t)(b0 + row) * HDIM + (kg - IDIM);
        sH = g_hhi[rbuf] + o; sL = g_hlo[rbuf] + o;
    }
    cp16(Ah + row * SA + kl, sH);
    cp16(Al + row * SA + kl, sL);
    // B: 2 x 16B per thread per array
#pragma unroll
    for (int u = 0; u < 2; u++) {
        int j2 = tid + u * THREADS;
        int n  = j2 >> 2;
        int kq = (j2 & 3) * 8;
        size_t o = ((size_t)nb * NT + n) * KDIM + kc * KC + kq;
        cp16(Bh + n * SA + kq, g_whi + o);
        cp16(Bl + n * SA + kq, g_wlo + o);
    }
}

// ------------- persistent LSTM kernel -------------
__global__ void __launch_bounds__(THREADS, 1)
lstm_kernel(const float* __restrict__ bias) {
    extern __shared__ unsigned char smem_raw[];
    __nv_bfloat16* sb = (__nv_bfloat16*)smem_raw;
    float* zs = (float*)(smem_raw + (size_t)2 * BUF_E * sizeof(__nv_bfloat16));

    const int tid  = threadIdx.x;
    const int warp = tid >> 5, lane = tid & 31;
    const int g  = lane >> 2, tq = lane & 3;
    const int wm = warp >> 2, wn = warp & 3;   // 2 x 4 warp grid
    const int cta = blockIdx.x;
    const int mb = cta >> 4, nb = cta & 15;
    const int b0 = mb * MB_TILE;
    const int hc0 = nb * HC;

    // bias for epilogue: q = wn, j = ni*8 + 2*tq + {0,1}
    float bq[4][2];
#pragma unroll
    for (int ni = 0; ni < 4; ni++) {
        int j0 = ni * 8 + 2 * tq;
        bq[ni][0] = bias[wn * HDIM + hc0 + j0];
        bq[ni][1] = bias[wn * HDIM + hc0 + j0 + 1];
    }

    // gate-phase mapping: j = tid&31, rows (tid>>5) + 8*r
    const int gj = tid & 31;
    const int grb = tid >> 5;

    float cst[8];
#pragma unroll
    for (int r = 0; r < 8; r++) cst[r] = 0.0f;

    float acc[2][4][4];

    for (int t = 0; t < TSEQ; t++) {
        const int rbuf = (t + 1) & 1;   // h_{t-1}
        const int wbuf = t & 1;         // h_t
#pragma unroll
        for (int mi = 0; mi < 2; mi++)
#pragma unroll
            for (int ni = 0; ni < 4; ni++)
#pragma unroll
                for (int c = 0; c < 4; c++) acc[mi][ni][c] = 0.0f;

        stage_chunk(0, sb, t, rbuf, b0, nb, tid);
        cp_commit();

        for (int kc = 0; kc < NKC; kc++) {
            cp_wait0();
            __syncthreads();
            if (kc + 1 < NKC) {
                stage_chunk(kc + 1, sb + ((kc + 1) & 1) * BUF_E, t, rbuf, b0, nb, tid);
                cp_commit();
            }
            const __nv_bfloat16* Ah = sb + (kc & 1) * BUF_E;
            const __nv_bfloat16* Al = Ah + ASZ_E;
            const __nv_bfloat16* Bh = Ah + 2 * ASZ_E;
            const __nv_bfloat16* Bl = Ah + 2 * ASZ_E + BSZ_E;

#pragma unroll
            for (int kk = 0; kk < 2; kk++) {
                const int kb = kk * 16 + 2 * tq;
                uint32_t ah[2][4], al[2][4];
#pragma unroll
                for (int mi = 0; mi < 2; mi++) {
                    const int r0 = (wm * 32 + mi * 16 + g) * SA;
                    ah[mi][0] = *(const uint32_t*)(Ah + r0 + kb);
                    ah[mi][1] = *(const uint32_t*)(Ah + r0 + 8 * SA + kb);
                    ah[mi][2] = *(const uint32_t*)(Ah + r0 + kb + 8);
                    ah[mi][3] = *(const uint32_t*)(Ah + r0 + 8 * SA + kb + 8);
                    al[mi][0] = *(const uint32_t*)(Al + r0 + kb);
                    al[mi][1] = *(const uint32_t*)(Al + r0 + 8 * SA + kb);
                    al[mi][2] = *(const uint32_t*)(Al + r0 + kb + 8);
                    al[mi][3] = *(const uint32_t*)(Al + r0 + 8 * SA + kb + 8);
                }
#pragma unroll
                for (int ni = 0; ni < 4; ni++) {
                    const int nn = (wn * 32 + ni * 8 + g) * SA;
                    uint32_t bh0 = *(const uint32_t*)(Bh + nn + kb);
                    uint32_t bh1 = *(const uint32_t*)(Bh + nn + kb + 8);
                    uint32_t bl0 = *(const uint32_t*)(Bl + nn + kb);
                    uint32_t bl1 = *(const uint32_t*)(Bl + nn + kb + 8);
#pragma unroll
                    for (int mi = 0; mi < 2; mi++) {
                        mma16816(acc[mi][ni], ah[mi], bh0, bh1);  // hi*hi
                        mma16816(acc[mi][ni], ah[mi], bl0, bl1);  // hi*lo
                        mma16816(acc[mi][ni], al[mi], bh0, bh1);  // lo*hi
                    }
                }
            }
        }

        // epilogue: z = acc + bias -> smem [row][q*33+j]
#pragma unroll
        for (int mi = 0; mi < 2; mi++) {
            const int r0 = wm * 32 + mi * 16 + g;
#pragma unroll
            for (int ni = 0; ni < 4; ni++) {
                const int base = wn * 33 + ni * 8 + 2 * tq;
                zs[r0 * ZSTR + base]           = acc[mi][ni][0] + bq[ni][0];
                zs[r0 * ZSTR + base + 1]       = acc[mi][ni][1] + bq[ni][1];
                zs[(r0 + 8) * ZSTR + base]     = acc[mi][ni][2] + bq[ni][0];
                zs[(r0 + 8) * ZSTR + base + 1] = acc[mi][ni][3] + bq[ni][1];
            }
        }
        __syncthreads();

        // gate math + h update (c-state in registers)
#pragma unroll
        for (int r = 0; r < 8; r++) {
            const int row = grb + 8 * r;
            float zg = zs[row * ZSTR + 0 * 33 + gj];
            float zi = zs[row * ZSTR + 1 * 33 + gj];
            float zf = zs[row * ZSTR + 2 * 33 + gj];
            float zo = zs[row * ZSTR + 3 * 33 + gj];
            float gg = tanh_(zg);
            float ii = sigf(zi);
            float ff = sigf(zf);
            float oo = sigf(zo);
            float c = gg * ii + cst[r] * ff;
            cst[r] = c;
            float h = tanh_(c) * oo;
            __nv_bfloat16 hi, lo;
            split_bf16(h, hi, lo);
            size_t off = (size_t)(b0 + row) * HDIM + hc0 + gj;
            g_hhi[wbuf][off] = hi;
            g_hlo[wbuf][off] = lo;
        }
        grid_barrier();
    }
}

// ------------- projection + softmax -------------
__global__ void proj_kernel(const float* __restrict__ Wp, const float* __restrict__ bp,
                            float* __restrict__ out) {
    __shared__ float hrow[HDIM];
    __shared__ float red[ODIM];
    const int b = blockIdx.x, o = threadIdx.x;
    const int fin = (TSEQ - 1) & 1;
    for (int k = o; k < HDIM; k += ODIM) {
        size_t off = (size_t)b * HDIM + k;
        hrow[k] = __bfloat162float(g_hhi[fin][off]) + __bfloat162float(g_hlo[fin][off]);
    }
    __syncthreads();
    float acc = bp[o];
    for (int k = 0; k < HDIM; k++)
        acc = fmaf(hrow[k], Wp[(size_t)k * ODIM + o], acc);
    red[o] = acc;
    __syncthreads();
    for (int s = 64; s > 0; s >>= 1) {
        if (o < s) red[o] = fmaxf(red[o], red[o + s]);
        __syncthreads();
    }
    float mx = red[0];
    __syncthreads();
    float e = expf(acc - mx);
    red[o] = e;
    __syncthreads();
    for (int s = 64; s > 0; s >>= 1) {
        if (o < s) red[o] += red[o + s];
        __syncthreads();
    }
    out[(size_t)b * ODIM + o] = e / red[0];
}

// ------------- launch -------------
extern "C" void kernel_launch(void* const* d_in, const int* in_sizes, int n_in,
                              void* d_out, int out_size) {
    const float* x  = (const float*)d_in[0];
    const float* Wx = (const float*)d_in[1];
    const float* Wh = (const float*)d_in[2];
    const float* b  = (const float*)d_in[3];
    const float* Wp = (const float*)d_in[4];
    const float* bp = (const float*)d_in[5];
    float* out = (float*)d_out;

    cudaFuncSetAttribute(lstm_kernel, cudaFuncAttributeMaxDynamicSharedMemorySize, SMEM_BYTES);

    {
        size_t n = (size_t)BSZ * TSEQ * IDIM;
        split_x_kernel<<<(unsigned)((n + 255) / 256), 256>>>(x);
    }
    {
        size_t n = (size_t)NB_CNT * NT * KDIM;
        pack_w_kernel<<<(unsigned)((n + 255) / 256), 256>>>(Wx, Wh);
    }
    {
        size_t n = (size_t)BSZ * HDIM;
        zero_h_kernel<<<(unsigned)((n + 255) / 256), 256>>>();
    }
    lstm_kernel<<<NCTA, THREADS, SMEM_BYTES>>>(b);
    proj_kernel<<<BSZ, ODIM>>>(Wp, bp, out);
}

// round 3
// speedup vs baseline: 1.0671x; 1.0671x over previous
#include <cuda_runtime.h>
#include <cuda_bf16.h>
#include <cstdint>

// Problem dims
#define BSZ   512
#define TSEQ  512
#define IDIM  128
#define HDIM  512
#define NGATE 2048
#define ODIM  128
#define KDIM  640   // I + H

// Tiling
#define MB_TILE 64      // batch rows per CTA
#define HC      32      // h-cols per CTA
#define NT      128     // z-cols per CTA (4 gates x HC)
#define NB_CNT  16      // HDIM / HC
#define NCTA    128
#define KC      32      // k chunk
#define NKC     20      // KDIM / KC
#define SA      40      // smem row stride (elements); 80B pitch -> conflict-free LDSM
#define ZSTR    132     // 4*33
#define THREADS 512     // 16 warps, 4x4 warp grid

#define ASZ_E   (MB_TILE*SA)            // 2560
#define BSZ_E   (NT*SA)                 // 5120
#define BUF_E   (2*ASZ_E + 2*BSZ_E)     // 15360 elems (Ahi,Alo,Bhi,Blo)
#define SMEM_BYTES (2*BUF_E*2 + MB_TILE*ZSTR*4)   // 61440 + 33792 = 95232

// ------------- device scratch (allocations are forbidden) -------------
__device__ __nv_bfloat16 g_xhi[(size_t)BSZ*TSEQ*IDIM];
__device__ __nv_bfloat16 g_xlo[(size_t)BSZ*TSEQ*IDIM];
__device__ __nv_bfloat16 g_whi[(size_t)NB_CNT*NT*KDIM];
__device__ __nv_bfloat16 g_wlo[(size_t)NB_CNT*NT*KDIM];
__device__ __nv_bfloat16 g_hhi[2][(size_t)BSZ*HDIM];
__device__ __nv_bfloat16 g_hlo[2][(size_t)BSZ*HDIM];
__device__ unsigned int  g_bar_count;
__device__ unsigned int  g_bar_gen;

// ------------- helpers -------------
__device__ __forceinline__ void split_bf16(float v, __nv_bfloat16& hi, __nv_bfloat16& lo) {
    hi = __float2bfloat16(v);
    lo = __float2bfloat16(v - __bfloat162float(hi));
}
__device__ __forceinline__ float sigf(float x) {
    return __fdividef(1.0f, 1.0f + __expf(-x));
}
__device__ __forceinline__ float tanh_(float x) {
    return 2.0f * sigf(2.0f * x) - 1.0f;
}
__device__ __forceinline__ void cp16(void* smem_dst, const void* gsrc) {
    uint32_t s = (uint32_t)__cvta_generic_to_shared(smem_dst);
    asm volatile("cp.async.cg.shared.global [%0], [%1], 16;\n" :: "r"(s), "l"(gsrc));
}
__device__ __forceinline__ void cp_commit() { asm volatile("cp.async.commit_group;\n"); }
__device__ __forceinline__ void cp_wait0() { asm volatile("cp.async.wait_group 0;\n"); }

__device__ __forceinline__ void ldsm4(uint32_t* r, const __nv_bfloat16* p) {
    uint32_t a = (uint32_t)__cvta_generic_to_shared(p);
    asm volatile("ldmatrix.sync.aligned.m8n8.x4.shared.b16 {%0,%1,%2,%3}, [%4];\n"
                 : "=r"(r[0]), "=r"(r[1]), "=r"(r[2]), "=r"(r[3]) : "r"(a));
}

__device__ __forceinline__ void mma16816(float* c, const uint32_t* a, uint32_t b0, uint32_t b1) {
    asm volatile(
        "mma.sync.aligned.m16n8k16.row.col.f32.bf16.bf16.f32 "
        "{%0,%1,%2,%3},{%4,%5,%6,%7},{%8,%9},{%0,%1,%2,%3};\n"
        : "+f"(c[0]), "+f"(c[1]), "+f"(c[2]), "+f"(c[3])
        : "r"(a[0]), "r"(a[1]), "r"(a[2]), "r"(a[3]), "r"(b0), "r"(b1));
}

__device__ __forceinline__ void grid_barrier() {
    __syncthreads();
    if (threadIdx.x == 0) {
        __threadfence();
        unsigned gen = *((volatile unsigned*)&g_bar_gen);
        unsigned a = atomicAdd(&g_bar_count, 1u);
        if (a == NCTA - 1u) {
            g_bar_count = 0u;
            __threadfence();
            atomicAdd(&g_bar_gen, 1u);
        } else {
            while (*((volatile unsigned*)&g_bar_gen) == gen) { __nanosleep(64); }
        }
        __threadfence();
    }
    __syncthreads();
}

// ------------- setup kernels -------------
__global__ void split_x_kernel(const float* __restrict__ x) {
    size_t idx = (size_t)blockIdx.x * blockDim.x + threadIdx.x;
    if (idx >= (size_t)BSZ * TSEQ * IDIM) return;
    __nv_bfloat16 hi, lo;
    split_bf16(x[idx], hi, lo);
    g_xhi[idx] = hi; g_xlo[idx] = lo;
}

// pack W=[Wx;Wh] to [nb][n][k] (k contiguous), n = q*32+j <-> col q*HDIM+nb*32+j
__global__ void pack_w_kernel(const float* __restrict__ Wx, const float* __restrict__ Wh) {
    size_t idx = (size_t)blockIdx.x * blockDim.x + threadIdx.x;
    if (idx >= (size_t)NB_CNT * NT * KDIM) return;
    int k  = (int)(idx % KDIM);
    int n  = (int)((idx / KDIM) % NT);
    int nb = (int)(idx / ((size_t)KDIM * NT));
    int q = n >> 5, j = n & 31;
    int col = q * HDIM + nb * HC + j;
    float v = (k < IDIM) ? Wx[(size_t)k * NGATE + col]
                         : Wh[(size_t)(k - IDIM) * NGATE + col];
    __nv_bfloat16 hi, lo;
    split_bf16(v, hi, lo);
    g_whi[idx] = hi; g_wlo[idx] = lo;
}

__global__ void zero_h_kernel() {
    size_t idx = (size_t)blockIdx.x * blockDim.x + threadIdx.x;
    if (idx >= (size_t)BSZ * HDIM) return;
    g_hhi[1][idx] = __float2bfloat16(0.0f);
    g_hlo[1][idx] = __float2bfloat16(0.0f);
}

// ------------- staging: one K-chunk (A 64x32 + B 128x32, hi & lo), 512 threads -------------
__device__ __forceinline__ void stage_chunk(int kc, __nv_bfloat16* buf,
                                            int t, int rbuf, int b0, int nb, int tid) {
    __nv_bfloat16* Ah = buf;
    __nv_bfloat16* Al = buf + ASZ_E;
    __nv_bfloat16* Bh = buf + 2 * ASZ_E;
    __nv_bfloat16* Bl = buf + 2 * ASZ_E + BSZ_E;
    // A: 256 slots per array; tid<256 -> hi, tid>=256 -> lo
    {
        int s   = tid & 255;
        int row = s >> 2;
        int kl  = (s & 3) * 8;
        int kg  = kc * KC + kl;
        const __nv_bfloat16* src;
        __nv_bfloat16* dst = (tid < 256 ? Ah : Al) + row * SA + kl;
        if (kg < IDIM) {
            size_t o = ((size_t)(b0 + row) * TSEQ + t) * IDIM + kg;
            src = (tid < 256 ? g_xhi : g_xlo) + o;
        } else {
            size_t o = (size_t)(b0 + row) * HDIM + (kg - IDIM);
            src = (tid < 256 ? g_hhi[rbuf] : g_hlo[rbuf]) + o;
        }
        cp16(dst, src);
    }
    // B: 512 slots per array; each thread does one hi and one lo transfer
    {
        int n  = tid >> 2;
        int kq = (tid & 3) * 8;
        size_t o = ((size_t)nb * NT + n) * KDIM + kc * KC + kq;
        cp16(Bh + n * SA + kq, g_whi + o);
        cp16(Bl + n * SA + kq, g_wlo + o);
    }
}

// ------------- persistent LSTM kernel -------------
__global__ void __launch_bounds__(THREADS, 1)
lstm_kernel(const float* __restrict__ bias) {
    extern __shared__ unsigned char smem_raw[];
    __nv_bfloat16* sb = (__nv_bfloat16*)smem_raw;
    float* zs = (float*)(smem_raw + (size_t)2 * BUF_E * sizeof(__nv_bfloat16));

    const int tid  = threadIdx.x;
    const int warp = tid >> 5, lane = tid & 31;
    const int g  = lane >> 2, tq = lane & 3;
    const int wm = warp >> 2, wn = warp & 3;   // 4 x 4 warp grid
    const int cta = blockIdx.x;
    const int mb = cta >> 4, nb = cta & 15;
    const int b0 = mb * MB_TILE;
    const int hc0 = nb * HC;
    const int mbase = wm * 16;

    // per-lane ldmatrix offsets (element units)
    const int lr = (lane & 7) + ((lane >> 3) & 1) * 8;  // row within 16
    const int lc = (lane >> 4) * 8;                     // k offset 0/8
    const int aoff  = (mbase + lr) * SA + lc;
    const int boff0 = (wn * 32 + lr) * SA + lc;
    const int boff1 = (wn * 32 + 16 + lr) * SA + lc;

    // bias for epilogue: gate q = wn, col j = ni*8 + 2*tq + {0,1}
    float bq[4][2];
#pragma unroll
    for (int ni = 0; ni < 4; ni++) {
        int j0 = ni * 8 + 2 * tq;
        bq[ni][0] = bias[wn * HDIM + hc0 + j0];
        bq[ni][1] = bias[wn * HDIM + hc0 + j0 + 1];
    }

    // gate-phase mapping: col j = tid&31, rows (tid>>5) + 16*r, r in 0..3
    const int gj  = tid & 31;
    const int grb = tid >> 5;

    float cst[4];
#pragma unroll
    for (int r = 0; r < 4; r++) cst[r] = 0.0f;

    float acc[4][4];

    for (int t = 0; t < TSEQ; t++) {
        const int rbuf = (t + 1) & 1;   // h_{t-1}
        const int wbuf = t & 1;         // h_t
#pragma unroll
        for (int ni = 0; ni < 4; ni++)
#pragma unroll
            for (int c = 0; c < 4; c++) acc[ni][c] = 0.0f;

        stage_chunk(0, sb, t, rbuf, b0, nb, tid);
        cp_commit();

        for (int kc = 0; kc < NKC; kc++) {
            cp_wait0();
            __syncthreads();
            if (kc + 1 < NKC) {
                stage_chunk(kc + 1, sb + ((kc + 1) & 1) * BUF_E, t, rbuf, b0, nb, tid);
                cp_commit();
            }
            const __nv_bfloat16* Ah = sb + (kc & 1) * BUF_E;
            const __nv_bfloat16* Al = Ah + ASZ_E;
            const __nv_bfloat16* Bh = Ah + 2 * ASZ_E;
            const __nv_bfloat16* Bl = Ah + 2 * ASZ_E + BSZ_E;

#pragma unroll
            for (int kk = 0; kk < 2; kk++) {
                const int kb = kk * 16;
                uint32_t ah[4], al[4], bh[8], bl[8];
                ldsm4(ah,     Ah + aoff  + kb);
                ldsm4(al,     Al + aoff  + kb);
                ldsm4(&bh[0], Bh + boff0 + kb);
                ldsm4(&bh[4], Bh + boff1 + kb);
                ldsm4(&bl[0], Bl + boff0 + kb);
                ldsm4(&bl[4], Bl + boff1 + kb);
                // pass-major: 4 independent accumulator chains per pass
#pragma unroll
                for (int ni = 0; ni < 4; ni++) {
                    const int p = (ni >> 1) * 4, o = ni & 1;
                    mma16816(acc[ni], ah, bh[p + o], bh[p + o + 2]);   // hi*hi
                }
#pragma unroll
                for (int ni = 0; ni < 4; ni++) {
                    const int p = (ni >> 1) * 4, o = ni & 1;
                    mma16816(acc[ni], ah, bl[p + o], bl[p + o + 2]);   // hi*lo
                }
#pragma unroll
                for (int ni = 0; ni < 4; ni++) {
                    const int p = (ni >> 1) * 4, o = ni & 1;
                    mma16816(acc[ni], al, bh[p + o], bh[p + o + 2]);   // lo*hi
                }
            }
        }

        // epilogue: z = acc + bias -> smem zs[row][q*33 + j]
        {
            const int r0 = mbase + g;
#pragma unroll
            for (int ni = 0; ni < 4; ni++) {
                const int base = wn * 33 + ni * 8 + 2 * tq;
                zs[r0 * ZSTR + base]           = acc[ni][0] + bq[ni][0];
                zs[r0 * ZSTR + base + 1]       = acc[ni][1] + bq[ni][1];
                zs[(r0 + 8) * ZSTR + base]     = acc[ni][2] + bq[ni][0];
                zs[(r0 + 8) * ZSTR + base + 1] = acc[ni][3] + bq[ni][1];
            }
        }
        __syncthreads();

        // gate math + h update (c-state in registers)
#pragma unroll
        for (int r = 0; r < 4; r++) {
            const int row = grb + 16 * r;
            float zg = zs[row * ZSTR + 0 * 33 + gj];
            float zi = zs[row * ZSTR + 1 * 33 + gj];
            float zf = zs[row * ZSTR + 2 * 33 + gj];
            float zo = zs[row * ZSTR + 3 * 33 + gj];
            float gg = tanh_(zg);
            float ii = sigf(zi);
            float ff = sigf(zf);
            float oo = sigf(zo);
            float c = gg * ii + cst[r] * ff;
            cst[r] = c;
            float h = tanh_(c) * oo;
            __nv_bfloat16 hi, lo;
            split_bf16(h, hi, lo);
            size_t off = (size_t)(b0 + row) * HDIM + hc0 + gj;
            g_hhi[wbuf][off] = hi;
            g_hlo[wbuf][off] = lo;
        }
        grid_barrier();
    }
}

// ------------- projection + softmax -------------
__global__ void proj_kernel(const float* __restrict__ Wp, const float* __restrict__ bp,
                            float* __restrict__ out) {
    __shared__ float hrow[HDIM];
    __shared__ float red[ODIM];
    const int b = blockIdx.x, o = threadIdx.x;
    const int fin = (TSEQ - 1) & 1;
    for (int k = o; k < HDIM; k += ODIM) {
        size_t off = (size_t)b * HDIM + k;
        hrow[k] = __bfloat162float(g_hhi[fin][off]) + __bfloat162float(g_hlo[fin][off]);
    }
    __syncthreads();
    float acc = bp[o];
    for (int k = 0; k < HDIM; k++)
        acc = fmaf(hrow[k], Wp[(size_t)k * ODIM + o], acc);
    red[o] = acc;
    __syncthreads();
    for (int s = 64; s > 0; s >>= 1) {
        if (o < s) red[o] = fmaxf(red[o], red[o + s]);
        __syncthreads();
    }
    float mx = red[0];
    __syncthreads();
    float e = expf(acc - mx);
    red[o] = e;
    __syncthreads();
    for (int s = 64; s > 0; s >>= 1) {
        if (o < s) red[o] += red[o + s];
        __syncthreads();
    }
    out[(size_t)b * ODIM + o] = e / red[0];
}

// ------------- launch -------------
extern "C" void kernel_launch(void* const* d_in, const int* in_sizes, int n_in,
                              void* d_out, int out_size) {
    const float* x  = (const float*)d_in[0];
    const float* Wx = (const float*)d_in[1];
    const float* Wh = (const float*)d_in[2];
    const float* b  = (const float*)d_in[3];
    const float* Wp = (const float*)d_in[4];
    const float* bp = (const float*)d_in[5];
    float* out = (float*)d_out;

    cudaFuncSetAttribute(lstm_kernel, cudaFuncAttributeMaxDynamicSharedMemorySize, SMEM_BYTES);

    {
        size_t n = (size_t)BSZ * TSEQ * IDIM;
        split_x_kernel<<<(unsigned)((n + 255) / 256), 256>>>(x);
    }
    {
        size_t n = (size_t)NB_CNT * NT * KDIM;
        pack_w_kernel<<<(unsigned)((n + 255) / 256), 256>>>(Wx, Wh);
    }
    {
        size_t n = (size_t)BSZ * HDIM;
        zero_h_kernel<<<(unsigned)((n + 255) / 256), 256>>>();
    }
    lstm_kernel<<<NCTA, THREADS, SMEM_BYTES>>>(b);
    proj_kernel<<<BSZ, ODIM>>>(Wp, bp, out);
}